// round 10
// baseline (speedup 1.0000x reference)
#include <cuda_runtime.h>
#include <math.h>

#define BATCH        2048
#define IN_DIM       4096
#define OUT_DIM      1024
#define N_EDGES_MAX  16384

#define BT           128    // batch-tile per gather block (1 float4 per lane)
#define NPB          8      // nodes (warps) per gather block

// Scratch (no allocations allowed): transposed x + CSR meta.
__device__ float g_xt[(size_t)IN_DIM * BATCH];   // 32 MB, x_t[s][b] (L2-resident)
__device__ int   g_offs[OUT_DIM + 1];
__device__ int2  g_edges[N_EDGES_MAX];           // (src, weight_bits)

// ---------------- Fused transpose + prologue ----------------
__global__ __launch_bounds__(256)
void transpose_prologue_kernel(const float* __restrict__ x,
                               const int* __restrict__ edge_src,
                               const float* __restrict__ weights,
                               const int* __restrict__ edge_dst,
                               int n_edges) {
    const int tx = threadIdx.x, ty = threadIdx.y;

    // ---- Embedded prologue (64 blocks x 256 threads = 16384 lanes) ----
    if (blockIdx.y == 0 && blockIdx.x < 64) {
        const int i = blockIdx.x * 256 + ty * 32 + tx;
        if (i < n_edges) {
            g_edges[i] = make_int2(edge_src[i], __float_as_int(weights[i]));
            const int d  = edge_dst[i];
            const int dp = (i == 0) ? -1 : edge_dst[i - 1];
            for (int o = dp + 1; o <= d; o++) g_offs[o] = i;
            if (i == n_edges - 1)
                for (int o = d + 1; o <= OUT_DIM; o++) g_offs[o] = n_edges;
        }
    }

    // ---- Transpose tile ----
    __shared__ float tile[32][33];
    const int c0 = blockIdx.x * 32;   // IN_DIM tile base
    const int b0 = blockIdx.y * 32;   // BATCH tile base
    #pragma unroll
    for (int i = 0; i < 4; i++)
        tile[ty + i * 8][tx] = x[(size_t)(b0 + ty + i * 8) * IN_DIM + c0 + tx];
    __syncthreads();
    #pragma unroll
    for (int i = 0; i < 4; i++)
        g_xt[(size_t)(c0 + ty + i * 8) * BATCH + b0 + tx] = tile[tx][ty + i * 8];
}

// ---------------- Gather: warp-per-node, shfl-broadcast edge meta ----------
__device__ __forceinline__ float4 fma4(float4 v, float w, float4 a) {
    a.x = fmaf(v.x, w, a.x);
    a.y = fmaf(v.y, w, a.y);
    a.z = fmaf(v.z, w, a.z);
    a.w = fmaf(v.w, w, a.w);
    return a;
}
__device__ __forceinline__ float act(float v) {
    float h = tanhf(v);
    return 1.0f / (1.0f + __expf(-h));
}

__global__ __launch_bounds__(NPB * 32, 6)   // cap regs ~42 -> 6 blocks/SM
void gather_kernel(float* __restrict__ out) {
    const int warp = threadIdx.x >> 5;
    const int lane = threadIdx.x & 31;
    const int o    = blockIdx.y * NPB + warp;          // node (warp-uniform)
    const int bq0  = blockIdx.x * (BT / 4);            // float4 base in batch

    const float4* __restrict__ xt4 = reinterpret_cast<const float4*>(g_xt);
    const int beg = g_offs[o];
    const int cnt = g_offs[o + 1] - beg;

    float4 acc = make_float4(0.f, 0.f, 0.f, 0.f);

    // Warp-cooperative edge fetch: one LDG.64 covers up to 32 edges, then
    // register-only shfl broadcasts (src, w). All x_t addresses are
    // register-derived -> the LDG.128s stream with no mem->addr dependency.
    for (int base = 0; base < cnt; base += 32) {
        const int rem = min(32, cnt - base);
        int2 ep = make_int2(0, 0);
        if (lane < rem) ep = __ldg(&g_edges[beg + base + lane]);

        int i = 0;
        for (; i + 3 < rem; i += 4) {
            int   s0 = __shfl_sync(0xFFFFFFFFu, ep.x, i + 0);
            float w0 = __int_as_float(__shfl_sync(0xFFFFFFFFu, ep.y, i + 0));
            int   s1 = __shfl_sync(0xFFFFFFFFu, ep.x, i + 1);
            float w1 = __int_as_float(__shfl_sync(0xFFFFFFFFu, ep.y, i + 1));
            int   s2 = __shfl_sync(0xFFFFFFFFu, ep.x, i + 2);
            float w2 = __int_as_float(__shfl_sync(0xFFFFFFFFu, ep.y, i + 2));
            int   s3 = __shfl_sync(0xFFFFFFFFu, ep.x, i + 3);
            float w3 = __int_as_float(__shfl_sync(0xFFFFFFFFu, ep.y, i + 3));
            float4 v0 = xt4[(size_t)s0 * (BATCH / 4) + bq0 + lane];
            float4 v1 = xt4[(size_t)s1 * (BATCH / 4) + bq0 + lane];
            float4 v2 = xt4[(size_t)s2 * (BATCH / 4) + bq0 + lane];
            float4 v3 = xt4[(size_t)s3 * (BATCH / 4) + bq0 + lane];
            acc = fma4(v0, w0, acc);
            acc = fma4(v1, w1, acc);
            acc = fma4(v2, w2, acc);
            acc = fma4(v3, w3, acc);
        }
        for (; i < rem; i++) {
            int   s = __shfl_sync(0xFFFFFFFFu, ep.x, i);
            float w = __int_as_float(__shfl_sync(0xFFFFFFFFu, ep.y, i));
            acc = fma4(xt4[(size_t)s * (BATCH / 4) + bq0 + lane], w, acc);
        }
    }

    // Activations
    acc.x = act(acc.x); acc.y = act(acc.y);
    acc.z = act(acc.z); acc.w = act(acc.w);

    // smem transpose: t[batch_in_tile][node_in_block] for coalesced stores
    __shared__ float t[BT][NPB + 1];
    {
        const int b = 4 * lane;
        t[b + 0][warp] = acc.x;
        t[b + 1][warp] = acc.y;
        t[b + 2][warp] = acc.z;
        t[b + 3][warp] = acc.w;
    }
    __syncthreads();

    // 256 threads store 128 rows x 8 floats: thread i -> row i>>1, half i&1
    {
        const int row  = threadIdx.x >> 1;         // 0..127
        const int half = (threadIdx.x & 1) * 4;    // 0 or 4
        const int b    = blockIdx.x * BT + row;
        float4 s = make_float4(t[row][half + 0], t[row][half + 1],
                               t[row][half + 2], t[row][half + 3]);
        *reinterpret_cast<float4*>(out + (size_t)b * OUT_DIM
                                   + blockIdx.y * NPB + half) = s;
    }
}

extern "C" void kernel_launch(void* const* d_in, const int* in_sizes, int n_in,
                              void* d_out, int out_size) {
    const float* x        = (const float*)d_in[0];   // [2048, 4096] f32
    const float* weights  = (const float*)d_in[1];   // [16384] f32
    const int*   edge_src = (const int*)d_in[2];     // [16384] i32
    const int*   edge_dst = (const int*)d_in[3];     // [16384] i32 (sorted)
    float*       out      = (float*)d_out;           // [2048, 1024] f32

    const int n_edges = in_sizes[1];

    // 1) Fused transpose + CSR-meta build (prologue hides under DRAM traffic)
    transpose_prologue_kernel<<<dim3(IN_DIM / 32, BATCH / 32), dim3(32, 8)>>>(
        x, edge_src, weights, edge_dst, n_edges);

    // 2) Gather: warp-per-node over batch tiles, all reads coalesced
    gather_kernel<<<dim3(BATCH / BT, OUT_DIM / NPB), NPB * 32>>>(out);
}